// round 13
// baseline (speedup 1.0000x reference)
#include <cuda_runtime.h>
#include <cstdint>
#include <math.h>

#define NIMG     8
#define GH       128
#define GW       128
#define NA       9
#define NANCH    (GH*GW*NA)      /* 147456 */
#define NC       86
#define CAPF     512             /* candidate capacity */
#define CAP      2048            /* full-fallback cap */
#define PRE_T    3.0f            /* expected count ~199 +/- 14; [128,512] huge margins */
#define MINC     128
#define TOPK     1000
#define MAXDET   100
#define SCORE_TH 0.5f
#define IOU_TH   0.75f
#define NMSW     128             /* IoU bit-matrix window */
#define NT       512             /* block size */
#define K1T      256             /* prefilter threads */
#define K1PER    8               /* anchors per prefilter thread (MLP=8) */
#define K1B      (NANCH / (K1T * K1PER))   /* 72 blocks/image -> 576 CTAs */
#define K2GRID   148             /* >= 148: defeats low-grid SM issue throttle */
#define NPAD     (K2GRID - NIMG)

typedef unsigned long long u64;
typedef unsigned int       u32;

__device__ u64 g_buf[NIMG][CAPF];
__device__ __align__(16) float g_rec[NIMG][CAPF][8];  /* di,dj,dh,dw,score,label,-,- */
__device__ int g_cnt[NIMG];
__device__ int g_fin;        /* consumers done counter (K2) */
__device__ int g_padexit;    /* pad exit counter (K2)      */
__device__ float g_dummy;

static __device__ __forceinline__ u64 pack_key(float s, int n) {
    // s >= 0.5 > 0 -> orderable bits = bits|sign. DESCENDING order; low word = ~n
    // gives "smaller index first" on ties (lax.top_k semantics). Keys are UNIQUE
    // (distinct n) -> rank is a permutation.
    u32 sb = __float_as_uint(s) | 0x80000000u;
    return ((u64)sb << 32) | (u32)(~n);
}

// ===================== K1: prefilter (DRAM-floor scan) + per-hit records =====================
__global__ __launch_bounds__(K1T, 1)
void prefilter_kernel(const float* __restrict__ in) {
    __shared__ uint4 hitlist[CAPF];   // appends gated by slot<CAPF => no overflow
    __shared__ int s_hc;

    const int img = blockIdx.y;
    const int tid = threadIdx.x;
    const float* ibase = in + (size_t)img * NANCH * NC;

    if (tid == 0) s_hc = 0;
    __syncthreads();

    const int n0 = (blockIdx.x * K1T + tid) * K1PER;
    const float* b = ibase + (size_t)n0 * NC + 5;
    float v[K1PER];
    #pragma unroll
    for (int k = 0; k < K1PER; k++) v[k] = __ldg(b + (size_t)k * NC);
    #pragma unroll
    for (int k = 0; k < K1PER; k++) {
        if (v[k] >= PRE_T) {
            int p = atomicAdd(&g_cnt[img], 1);
            if (p < CAPF) {
                g_buf[img][p] = pack_key(v[k], n0 + k);
                int h = atomicAdd(&s_hc, 1);
                hitlist[h] = make_uint4((u32)p, (u32)(n0 + k), __float_as_uint(v[k]), 0u);
            }
        }
    }
    __syncthreads();

    // post-pass: one WARP per hit -> parallel class argmax + box decode -> g_rec
    const int hc = s_hc;
    const int w = tid >> 5, lane = tid & 31;
    for (int h = w; h < hc; h += K1T / 32) {
        uint4 e = hitlist[h];
        const int n = (int)e.y;
        const float* row = ibase + (size_t)n * NC;
        float bv = __ldg(row + 6 + lane);
        int bidx = lane;
        float v1 = __ldg(row + 6 + 32 + lane);
        float v2 = (lane < 16) ? __ldg(row + 6 + 64 + lane) : -1e38f;
        if (v1 > bv) { bv = v1; bidx = 32 + lane; }
        if (v2 > bv) { bv = v2; bidx = 64 + lane; }
        #pragma unroll
        for (int off = 16; off; off >>= 1) {
            float ov = __shfl_down_sync(0xffffffffu, bv, off);
            int   oi = __shfl_down_sync(0xffffffffu, bidx, off);
            if (ov > bv || (ov == bv && oi < bidx)) { bv = ov; bidx = oi; }
        }
        if (lane == 0) {
            int a = n % NA;
            int cell = n / NA;
            int gj = cell % GW;
            int gi = cell / GW;
            int si = a / 3, ri = a % 3;
            float s  = 0.5f * (float)(1 << si);
            float r  = 0.5f * (float)(1 << ri);
            float sr = sqrtf(r);
            float ah = (s * sr) * 0.03125f;          // ANCHOR_BASE_CELLS / 128
            float aw = (s / sr) * 0.03125f;
            float ci = ((float)gi + 0.5f) * (1.0f / 128.0f);
            float cj = ((float)gj + 0.5f) * (1.0f / 128.0f);
            float2 t01 = *(const float2*)row;
            float2 t23 = *(const float2*)(row + 2);
            float di = ci + t01.x * ah;
            float dj = cj + t01.y * aw;
            float dh = ah * expf(t23.x);
            float dw = aw * expf(t23.y);
            float* rec = &g_rec[img][e.x][0];
            *(float4*)rec       = make_float4(di, dj, dh, dw);
            *(float2*)(rec + 4) = make_float2(__uint_as_float(e.z), (float)bidx);
        }
    }
}

// ===================== K2: rank sort + NMS + output, grid padded to 148 =====================
__global__ __launch_bounds__(NT, 1)
void topk_nms_kernel(const float* __restrict__ in, float* __restrict__ out) {
    __shared__ __align__(16) u64 keys[CAP];          // sorted keys / overlaid by cor[]
    __shared__ u32  pay[CAPF];
    __shared__ __align__(16) float4 s_rec[CAPF * 2]; // smem copy of g_rec (fast path)
    __shared__ __align__(16) float4 c_box[1024];     // aliases rank-input keys
    __shared__ float c_score[1024];
    __shared__ float c_lab[1024];
    __shared__ int   c_idx[1024];                    // full-fallback only
    __shared__ __align__(16) u32 rowsw[NMSW + 1][4];
    __shared__ int   kept_rank[MAXDET];
    __shared__ int   s_nk;
    __shared__ int   s_fcnt;
    __shared__ int   s_flag;
    __shared__ u32   s_any;

    const int tid = threadIdx.x;
    const int lane = tid & 31;

    // ---------------- pad CTAs: busy-spin keeping SMs active until consumers finish ----------------
    if (blockIdx.x >= NIMG) {
        float x = (float)(tid + 1);
        for (;;) {
            int f = 0;
            if (lane == 0) f = *(volatile int*)&g_fin;
            f = __shfl_sync(0xffffffffu, f, 0);
            if (f >= NIMG) break;
            #pragma unroll
            for (int i = 0; i < 256; i++) x = fmaf(x, 1.0000001f, 1e-9f);
        }
        if (x == 1.2345e-33f) g_dummy = x;           // unreachable: keeps busywork alive
        __syncthreads();
        if (tid == 0) {
            int e = atomicAdd(&g_padexit, 1);
            if (e == NPAD - 1) { g_padexit = 0; g_fin = 0; __threadfence(); }  // last pad resets for replay
        }
        return;
    }

    // ---------------- consumer CTAs (one per image) ----------------
    const int img = blockIdx.x;
    const float* ibase = in + (size_t)img * NANCH * NC;
    float4* cor = (float4*)keys;
    u64* keys_in = (u64*)c_box;                      // phase-disjoint alias (rank phase only)

    int cnt = g_cnt[img];
    __syncthreads();
    if (tid == 0) g_cnt[img] = 0;        // reset for next replay (stream-ordered)

    bool full = !(cnt >= MINC && cnt <= CAPF);
    int M = 0;

    if (!full) {
        // ---- FAST PATH: rank sort (2 barriers) ----
        M = cnt;
        for (int i = tid; i < cnt; i += NT) keys_in[i] = g_buf[img][i];
        {
            const float4* src = (const float4*)&g_rec[img][0][0];
            for (int i = tid; i < cnt * 2; i += NT) s_rec[i] = src[i];
        }
        __syncthreads();

        if (tid < cnt) {
            u64 mine = keys_in[tid];
            int rank = 0;
            #pragma unroll 8
            for (int j = 0; j < cnt; j++) rank += (keys_in[j] > mine);
            keys[rank] = mine;
            pay[rank]  = (u32)tid;       // payload = g_buf/g_rec slot
        }
        __syncthreads();
    } else {
        // ---- FULL EXACT PATH (statistically never) ----
        if (tid == 0) s_fcnt = 0;
        for (int i = tid; i < CAP; i += NT) keys[i] = 0ull;
        __syncthreads();
        for (int n = tid; n < NANCH; n += NT) {
            float s = ibase[(size_t)n * NC + 5];
            if (s >= SCORE_TH) {
                int pos = atomicAdd(&s_fcnt, 1);
                if (pos < CAP) keys[pos] = pack_key(s, n);
            }
        }
        __syncthreads();
        M = min(min(s_fcnt, CAP), TOPK);
        for (int k = 2; k <= CAP; k <<= 1)
            for (int j = k >> 1; j; j >>= 1) {
                for (int t = tid; t < CAP / 2; t += NT) {
                    int i = ((t & ~(j - 1)) << 1) | (t & (j - 1));
                    int p = i | j;
                    u64 a = keys[i], bb = keys[p];
                    bool desc = ((i & k) == 0);
                    if (desc ? (a < bb) : (a > bb)) { keys[i] = bb; keys[p] = a; }
                }
                __syncthreads();
            }
    }

    // ---- decode, bit-matrix NMS, scan; with exactness post-check loop ----
    for (int attempt = 0; attempt < 2; ++attempt) {
        u64 ka = (tid < M)      ? keys[tid]      : 0ull;
        u64 kb = (tid + NT < M) ? keys[tid + NT] : 0ull;
        u32 pa = (!full && tid < M) ? pay[tid] : 0u;
        __syncthreads();

        if (!full) {
            if (tid < M) {
                float4 r0 = s_rec[2 * pa];
                float4 r1 = s_rec[2 * pa + 1];
                c_box[tid]   = r0;
                cor[tid]     = make_float4(r0.x - r0.z * 0.5f, r0.y - r0.w * 0.5f,
                                           r0.x + r0.z * 0.5f, r0.y + r0.w * 0.5f);
                c_score[tid] = r1.x;
                c_lab[tid]   = r1.y;
            }
        } else {
            #pragma unroll
            for (int half = 0; half < 2; ++half) {
                int i = tid + half * NT;
                u64 kk = half ? kb : ka;
                if (i < M) {
                    int n = (int)(~(u32)kk);
                    float score = __uint_as_float((u32)(kk >> 32) & 0x7fffffffu);
                    int a = n % NA;
                    int cell = n / NA;
                    int gj = cell % GW;
                    int gi = cell / GW;
                    int si = a / 3, ri = a % 3;
                    float s  = 0.5f * (float)(1 << si);
                    float r  = 0.5f * (float)(1 << ri);
                    float sr = sqrtf(r);
                    float ah = (s * sr) * 0.03125f;
                    float aw = (s / sr) * 0.03125f;
                    float ci = ((float)gi + 0.5f) * (1.0f / 128.0f);
                    float cj = ((float)gj + 0.5f) * (1.0f / 128.0f);
                    const float* t = ibase + (size_t)n * NC;
                    float di = ci + t[0] * ah;
                    float dj = cj + t[1] * aw;
                    float dh = ah * expf(t[2]);
                    float dw = aw * expf(t[3]);
                    c_box[i]   = make_float4(di, dj, dh, dw);
                    cor[i]     = make_float4(di - dh * 0.5f, dj - dw * 0.5f,
                                             di + dh * 0.5f, dj + dw * 0.5f);
                    c_score[i] = score;
                    c_idx[i]   = n;
                }
            }
        }
        if (tid == 0) s_any = 0;
        __syncthreads();

        // IoU suppression bit-matrix over first NMSW candidates
        const int Wlim = min(M, NMSW);
        {
            int rrr = tid >> 2, wi = tid & 3;
            u32 mask = 0;
            if (rrr < Wlim) {
                float4 a = cor[rrr];
                float aar = (a.z - a.x) * (a.w - a.y);
                int cbase = wi * 32;
                #pragma unroll 4
                for (int b = 0; b < 32; b++) {
                    int c = cbase + b;
                    if (c > rrr && c < Wlim) {
                        float4 bb = cor[c];
                        float ti = fmaxf(a.x, bb.x), tj = fmaxf(a.y, bb.y);
                        float bi = fminf(a.z, bb.z), bj = fminf(a.w, bb.w);
                        float inter = fmaxf(bi - ti, 0.0f) * fmaxf(bj - tj, 0.0f);
                        float bar = (bb.z - bb.x) * (bb.w - bb.y);
                        float uni = aar + bar - inter;
                        if (inter / fmaxf(uni, 1e-12f) > IOU_TH) mask |= (1u << b);
                    }
                }
            }
            rowsw[rrr][wi] = mask;
            if (tid < 4) rowsw[NMSW][tid] = 0;       // prefetch pad
            if (mask) atomicOr(&s_any, 1u);          // rare
        }
        __syncthreads();

        if (s_any == 0) {
            // zero suppression matrix => greedy keeps the prefix (exact)
            int nk = min(Wlim, MAXDET);
            if (tid < nk) kept_rank[tid] = tid;
            if (tid == 0) s_nk = nk;
        } else if (tid == 0) {
            const uint4* rv = (const uint4*)rowsw;
            u32 s0 = 0, s1 = 0, s2 = 0, s3 = 0;
            int nk = 0;
            uint4 rr = rv[0];
            for (int c = 0; c < Wlim && nk < MAXDET; ++c) {
                uint4 cur = rr;
                rr = rv[c + 1];
                u32 sw = (c < 64) ? ((c < 32) ? s0 : s1) : ((c < 96) ? s2 : s3);
                if (!((sw >> (c & 31)) & 1u)) {
                    kept_rank[nk++] = c;
                    s0 |= cur.x; s1 |= cur.y; s2 |= cur.z; s3 |= cur.w;
                }
            }
            s_nk = nk;
        }
        __syncthreads();

        // rare: continue serial greedy NMS past the window
        if (s_nk < MAXDET && M > Wlim) {
            if (tid < 32) {
                int nk = s_nk;
                float kc0[4], kc1[4], kc2[4], kc3[4], kar[4];
                #pragma unroll
                for (int sdx = 0; sdx < 4; ++sdx) {
                    int k = sdx * 32 + lane;
                    if (k < nk) {
                        float4 a = cor[kept_rank[k]];
                        kc0[sdx] = a.x; kc1[sdx] = a.y; kc2[sdx] = a.z; kc3[sdx] = a.w;
                        kar[sdx] = (a.z - a.x) * (a.w - a.y);
                    }
                }
                #pragma unroll 1
                for (int c = Wlim; c < M && nk < MAXDET; ++c) {
                    float4 a = cor[c];
                    float ar = (a.z - a.x) * (a.w - a.y);
                    bool pred = false;
                    #pragma unroll
                    for (int sdx = 0; sdx < 4; ++sdx) {
                        int k = sdx * 32 + lane;
                        if (k < nk) {
                            float ti = fmaxf(a.x, kc0[sdx]);
                            float tj = fmaxf(a.y, kc1[sdx]);
                            float bi = fminf(a.z, kc2[sdx]);
                            float bj = fminf(a.w, kc3[sdx]);
                            float inter = fmaxf(bi - ti, 0.0f) * fmaxf(bj - tj, 0.0f);
                            float uni = kar[sdx] + ar - inter;
                            pred |= (inter / fmaxf(uni, 1e-12f)) > IOU_TH;
                        }
                    }
                    if (!__ballot_sync(0xffffffffu, pred)) {
                        int slot = nk >> 5, ln = nk & 31;
                        if (lane == ln) {
                            #pragma unroll
                            for (int sdx = 0; sdx < 4; ++sdx) {
                                if (slot == sdx) {
                                    kc0[sdx] = a.x; kc1[sdx] = a.y;
                                    kc2[sdx] = a.z; kc3[sdx] = a.w; kar[sdx] = ar;
                                }
                            }
                            kept_rank[nk] = c;
                        }
                        nk++;
                    }
                }
                if (lane == 0) s_nk = nk;
            }
            __syncthreads();
        }

        // exactness post-check: fast set exhausted with <100 kept -> redo on full set
        if (tid == 0) s_flag = (!full && attempt == 0 && s_nk < MAXDET) ? 1 : 0;
        __syncthreads();
        if (!s_flag) break;

        full = true;
        if (tid == 0) s_fcnt = 0;
        __syncthreads();
        for (int i = tid; i < CAP; i += NT) keys[i] = 0ull;
        __syncthreads();
        for (int n = tid; n < NANCH; n += NT) {
            float s = ibase[(size_t)n * NC + 5];
            if (s >= SCORE_TH) {
                int pos = atomicAdd(&s_fcnt, 1);
                if (pos < CAP) keys[pos] = pack_key(s, n);
            }
        }
        __syncthreads();
        M = min(min(s_fcnt, CAP), TOPK);
        for (int k = 2; k <= CAP; k <<= 1)
            for (int j = k >> 1; j; j >>= 1) {
                for (int t = tid; t < CAP / 2; t += NT) {
                    int i = ((t & ~(j - 1)) << 1) | (t & (j - 1));
                    int p = i | j;
                    u64 a = keys[i], bb = keys[p];
                    bool desc = ((i & k) == 0);
                    if (desc ? (a < bb) : (a > bb)) { keys[i] = bb; keys[p] = a; }
                }
                __syncthreads();
            }
    }

    // ---- epilogue ----
    const int nk = s_nk;
    if (!full) {
        if (tid < MAXDET) {
            float* o = out + (size_t)img * MAXDET * 6 + tid * 6;
            if (tid < nk) {
                int c = kept_rank[tid];
                float4 bx = c_box[c];
                o[0] = bx.x; o[1] = bx.y; o[2] = bx.z; o[3] = bx.w;
                o[4] = c_lab[c];
                o[5] = c_score[c];
            } else {
                o[0] = 0.0f; o[1] = 0.0f; o[2] = 0.0f;
                o[3] = 0.0f; o[4] = 0.0f; o[5] = 0.0f;
            }
        }
    } else {
        #pragma unroll 1
        for (int row = tid >> 3; row < MAXDET; row += NT / 8) {
            const int sub = tid & 7;
            float* o = out + (size_t)img * MAXDET * 6 + row * 6;
            const bool live = row < nk;
            int c = live ? kept_rank[row] : 0;
            int n = live ? c_idx[c] : 0;
            float bv = -1e38f; int bidx = 1 << 30;
            if (live) {
                const float* cls = ibase + (size_t)n * NC + 6;
                #pragma unroll
                for (int t = 0; t < 10; t++) {
                    int cc = sub + t * 8;
                    float v = __ldg(cls + cc);
                    if (v > bv) { bv = v; bidx = cc; }
                }
            }
            #pragma unroll
            for (int off = 4; off; off >>= 1) {
                float ov = __shfl_down_sync(0xffffffffu, bv, off, 8);
                int   oi = __shfl_down_sync(0xffffffffu, bidx, off, 8);
                if (ov > bv || (ov == bv && oi < bidx)) { bv = ov; bidx = oi; }
            }
            if (live) {
                if (sub == 0) {
                    float4 bx = c_box[c];
                    o[0] = bx.x; o[1] = bx.y; o[2] = bx.z; o[3] = bx.w;
                    o[4] = (float)bidx;
                    o[5] = c_score[c];
                }
            } else {
                if (sub < 6) o[sub] = 0.0f;
            }
        }
    }

    // signal pads: this consumer is done
    __syncthreads();
    if (tid == 0) { __threadfence(); atomicAdd(&g_fin, 1); }
}

extern "C" void kernel_launch(void* const* d_in, const int* in_sizes, int n_in,
                              void* d_out, int out_size) {
    (void)in_sizes; (void)n_in; (void)out_size;
    const float* in = (const float*)d_in[0];
    float* out = (float*)d_out;

    prefilter_kernel<<<dim3(K1B, NIMG), K1T>>>(in);
    topk_nms_kernel<<<K2GRID, NT>>>(in, out);
}

// round 14
// speedup vs baseline: 1.1373x; 1.1373x over previous
#include <cuda_runtime.h>
#include <cstdint>
#include <math.h>

#define NIMG     8
#define GH       128
#define GW       128
#define NA       9
#define NANCH    (GH*GW*NA)      /* 147456 */
#define NC       86
#define CAPF     512             /* candidate capacity */
#define CAP      2048            /* full-fallback cap */
#define PRE_T    3.0f            /* expected count ~199 +/- 14; [128,256] at -5/+4 sigma */
#define MINC     128
#define TOPK     1000
#define MAXDET   100
#define SCORE_TH 0.5f
#define IOU_TH   0.75f
#define NMSW     128             /* IoU bit-matrix window */
#define NT       512             /* block size */
#define K1T      512             /* prefilter threads */
#define K1PER    16              /* anchors per prefilter thread (front-batched MLP=16) */
#define K1B      (NANCH / (K1T * K1PER))   /* 18 blocks/image -> 144 CTAs = ONE wave */

typedef unsigned long long u64;
typedef unsigned int       u32;

__device__ u64 g_buf[NIMG][CAPF];
__device__ __align__(16) float g_rec[NIMG][CAPF][8];  /* di,dj,dh,dw,score,label,-,- */
__device__ int g_cnt[NIMG];

static __device__ __forceinline__ u64 pack_key(float s, int n) {
    // s >= 0.5 > 0 -> orderable bits = bits|sign. DESCENDING sort; low word = ~n
    // gives "smaller index first" on ties (lax.top_k semantics).
    u32 sb = __float_as_uint(s) | 0x80000000u;
    return ((u64)sb << 32) | (u32)(~n);
}

// ===================== K1: single-wave prefilter (DRAM-floor scan) + per-hit records =====================
__global__ __launch_bounds__(K1T, 1)
void prefilter_kernel(const float* __restrict__ in) {
    __shared__ uint4 hitlist[CAPF];   // appends gated by slot<CAPF => no overflow
    __shared__ int s_hc;

    const int img = blockIdx.y;
    const int tid = threadIdx.x;
    const float* ibase = in + (size_t)img * NANCH * NC;

    if (tid == 0) s_hc = 0;
    __syncthreads();

    // front-batched MLP=16 scan of this CTA's 8192-anchor slice
    const int base = blockIdx.x * (K1T * K1PER);
    float v[K1PER];
    #pragma unroll
    for (int k = 0; k < K1PER; k++)
        v[k] = __ldg(ibase + (size_t)(base + tid + k * K1T) * NC + 5);
    #pragma unroll
    for (int k = 0; k < K1PER; k++) {
        if (v[k] >= PRE_T) {
            int n = base + tid + k * K1T;
            int p = atomicAdd(&g_cnt[img], 1);
            if (p < CAPF) {
                g_buf[img][p] = pack_key(v[k], n);
                int h = atomicAdd(&s_hc, 1);
                hitlist[h] = make_uint4((u32)p, (u32)n, __float_as_uint(v[k]), 0u);
            }
        }
    }
    __syncthreads();

    // post-pass: one WARP per hit -> parallel class argmax + box decode -> g_rec
    const int hc = s_hc;                 // ~14 per CTA typically
    const int w = tid >> 5, lane = tid & 31;
    for (int h = w; h < hc; h += K1T / 32) {
        uint4 e = hitlist[h];
        const int n = (int)e.y;
        const float* row = ibase + (size_t)n * NC;
        float bv = __ldg(row + 6 + lane);
        int bidx = lane;
        float v1 = __ldg(row + 6 + 32 + lane);
        float v2 = (lane < 16) ? __ldg(row + 6 + 64 + lane) : -1e38f;
        if (v1 > bv) { bv = v1; bidx = 32 + lane; }
        if (v2 > bv) { bv = v2; bidx = 64 + lane; }
        #pragma unroll
        for (int off = 16; off; off >>= 1) {
            float ov = __shfl_down_sync(0xffffffffu, bv, off);
            int   oi = __shfl_down_sync(0xffffffffu, bidx, off);
            if (ov > bv || (ov == bv && oi < bidx)) { bv = ov; bidx = oi; }
        }
        if (lane == 0) {
            int a = n % NA;
            int cell = n / NA;
            int gj = cell % GW;
            int gi = cell / GW;
            int si = a / 3, ri = a % 3;
            float s  = 0.5f * (float)(1 << si);
            float r  = 0.5f * (float)(1 << ri);
            float sr = sqrtf(r);
            float ah = (s * sr) * 0.03125f;          // ANCHOR_BASE_CELLS / 128
            float aw = (s / sr) * 0.03125f;
            float ci = ((float)gi + 0.5f) * (1.0f / 128.0f);
            float cj = ((float)gj + 0.5f) * (1.0f / 128.0f);
            float2 t01 = *(const float2*)row;
            float2 t23 = *(const float2*)(row + 2);
            float di = ci + t01.x * ah;
            float dj = cj + t01.y * aw;
            float dh = ah * expf(t23.x);
            float dw = aw * expf(t23.y);
            float* rec = &g_rec[img][e.x][0];
            *(float4*)rec       = make_float4(di, dj, dh, dw);
            *(float2*)(rec + 4) = make_float2(__uint_as_float(e.z), (float)bidx);
        }
    }
}

// ===================== K2: R9-exact — register bitonic + smem-prefetched records + NMS =====================
static __device__ __forceinline__ void shfl_cmp_kv(u64& k, u32& p, int j, bool desc, int lane) {
    u64 ok = __shfl_xor_sync(0xffffffffu, k, j);
    u32 op = __shfl_xor_sync(0xffffffffu, p, j);
    bool upper = (lane & j) == 0;                   // smaller-index position
    bool keep_max = (upper == desc);
    bool mine_max = k > ok;
    if (keep_max != mine_max) { k = ok; p = op; }
}

__global__ __launch_bounds__(NT, 1)
void topk_nms_kernel(const float* __restrict__ in, float* __restrict__ out) {
    __shared__ __align__(16) u64 keys[CAP];          // sorted keys; overlaid by cor[] after decode
    __shared__ u32  pay[CAPF];
    __shared__ __align__(16) float4 s_rec[CAPF * 2]; // smem copy of g_rec (fast path)
    __shared__ __align__(16) float4 c_box[1024];
    __shared__ float c_score[1024];
    __shared__ float c_lab[1024];
    __shared__ int   c_idx[1024];                    // full-fallback only
    __shared__ __align__(16) u32 rowsw[NMSW + 1][4];
    __shared__ int   kept_rank[MAXDET];
    __shared__ int   s_nk;
    __shared__ int   s_fcnt;
    __shared__ int   s_flag;
    __shared__ u32   s_any;

    const int img = blockIdx.x;
    const int tid = threadIdx.x;
    const int w = tid >> 5, lane = tid & 31;
    const float* ibase = in + (size_t)img * NANCH * NC;
    float4* cor = (float4*)keys;

    int cnt = g_cnt[img];
    __syncthreads();
    if (tid == 0) g_cnt[img] = 0;        // reset for next replay (stream-ordered)

    bool full = !(cnt >= MINC && cnt <= CAPF);
    int M = 0;
    int S = (cnt <= 256) ? 256 : 512;    // sort width (pow2 >= cnt)
    const int NWS = S / 64;              // warps doing the register sort

    if (!full) {
        M = cnt;
        if (w < NWS) {
            // ---- gather + per-warp 64-element register bitonic sort (block w desc iff w even) ----
            int i0 = 64 * w + lane;
            u32 xp = i0, yp = i0 + 32;
            u64 x = (i0      < cnt) ? g_buf[img][i0]      : 0ull;
            u64 y = (i0 + 32 < cnt) ? g_buf[img][i0 + 32] : 0ull;

            const bool block_desc = ((w & 1) == 0);
            const bool flip = !block_desc;
            #pragma unroll
            for (int k = 2; k <= 16; k <<= 1)
                #pragma unroll
                for (int j = k >> 1; j; j >>= 1) {
                    bool d = (((lane & k) == 0) != flip);
                    shfl_cmp_kv(x, xp, j, d, lane);
                    shfl_cmp_kv(y, yp, j, d, lane);
                }
            { // k=32: halves opposite directions
                bool dx = !flip, dy = flip;
                #pragma unroll
                for (int j = 16; j; j >>= 1) { shfl_cmp_kv(x, xp, j, dx, lane); shfl_cmp_kv(y, yp, j, dy, lane); }
            }
            { // k=64
                bool d = block_desc;
                bool xmax = x > y;
                if (xmax != d) { u64 tk = x; x = y; y = tk; u32 tp = xp; xp = yp; yp = tp; }
                #pragma unroll
                for (int j = 16; j; j >>= 1) { shfl_cmp_kv(x, xp, j, d, lane); shfl_cmp_kv(y, yp, j, d, lane); }
            }
            keys[64 * w + lane] = x;        pay[64 * w + lane] = xp;
            keys[64 * w + 32 + lane] = y;   pay[64 * w + 32 + lane] = yp;
        } else {
            // ---- idle warps: prefetch g_rec (slots 0..cnt) into smem (L2 -> LDS) ----
            int t0 = tid - NWS * 32;
            int nthr = NT - NWS * 32;
            const float4* src = (const float4*)&g_rec[img][0][0];
            for (int i = t0; i < cnt * 2; i += nthr) s_rec[i] = src[i];
        }
        __syncthreads();

        // ---- cross-warp merge phases k=128..S; j<=32 fused into shfl segments ----
        #pragma unroll 1
        for (int k = 128; k <= S; k <<= 1) {
            #pragma unroll 1
            for (int j = k >> 1; j >= 64; j >>= 1) {
                if (tid < S / 2) {
                    int i = ((tid & ~(j - 1)) << 1) | (tid & (j - 1));
                    int p2 = i | j;
                    u64 a = keys[i], bb = keys[p2];
                    bool desc = ((i & k) == 0);
                    if (desc ? (a < bb) : (a > bb)) {
                        u32 ap = pay[i], bp = pay[p2];
                        keys[i] = bb; keys[p2] = a;
                        pay[i] = bp; pay[p2] = ap;
                    }
                }
                __syncthreads();
            }
            if (w < NWS) {
                u64 xx = keys[64 * w + lane];        u32 xxp = pay[64 * w + lane];
                u64 yy = keys[64 * w + 32 + lane];   u32 yyp = pay[64 * w + 32 + lane];
                bool d = (((64 * w) & k) == 0);
                bool xmax = xx > yy;
                if (xmax != d) { u64 tk = xx; xx = yy; yy = tk; u32 tp = xxp; xxp = yyp; yyp = tp; }
                #pragma unroll
                for (int j = 16; j; j >>= 1) { shfl_cmp_kv(xx, xxp, j, d, lane); shfl_cmp_kv(yy, yyp, j, d, lane); }
                keys[64 * w + lane] = xx;        pay[64 * w + lane] = xxp;
                keys[64 * w + 32 + lane] = yy;   pay[64 * w + 32 + lane] = yyp;
            }
            __syncthreads();
        }
    } else {
        // ---- FULL EXACT PATH (statistically never) ----
        if (tid == 0) s_fcnt = 0;
        for (int i = tid; i < CAP; i += NT) keys[i] = 0ull;
        __syncthreads();
        for (int n = tid; n < NANCH; n += NT) {
            float s = ibase[(size_t)n * NC + 5];
            if (s >= SCORE_TH) {
                int pos = atomicAdd(&s_fcnt, 1);
                if (pos < CAP) keys[pos] = pack_key(s, n);
            }
        }
        __syncthreads();
        M = min(min(s_fcnt, CAP), TOPK);
        for (int k = 2; k <= CAP; k <<= 1)
            for (int j = k >> 1; j; j >>= 1) {
                for (int t = tid; t < CAP / 2; t += NT) {
                    int i = ((t & ~(j - 1)) << 1) | (t & (j - 1));
                    int p = i | j;
                    u64 a = keys[i], bb = keys[p];
                    bool desc = ((i & k) == 0);
                    if (desc ? (a < bb) : (a > bb)) { keys[i] = bb; keys[p] = a; }
                }
                __syncthreads();
            }
    }

    // ---- decode, bit-matrix NMS, scan; with exactness post-check loop ----
    for (int attempt = 0; attempt < 2; ++attempt) {
        u64 ka = (tid < M)      ? keys[tid]      : 0ull;
        u64 kb = (tid + NT < M) ? keys[tid + NT] : 0ull;
        u32 pa = (!full && tid < M) ? pay[tid] : 0u;
        __syncthreads();

        if (!full) {
            if (tid < M) {      // records in smem (prefetched during sort)
                float4 r0 = s_rec[2 * pa];
                float4 r1 = s_rec[2 * pa + 1];
                c_box[tid]   = r0;
                cor[tid]     = make_float4(r0.x - r0.z * 0.5f, r0.y - r0.w * 0.5f,
                                           r0.x + r0.z * 0.5f, r0.y + r0.w * 0.5f);
                c_score[tid] = r1.x;
                c_lab[tid]   = r1.y;
            }
        } else {
            #pragma unroll
            for (int half = 0; half < 2; ++half) {
                int i = tid + half * NT;
                u64 kk = half ? kb : ka;
                if (i < M) {
                    int n = (int)(~(u32)kk);
                    float score = __uint_as_float((u32)(kk >> 32) & 0x7fffffffu);
                    int a = n % NA;
                    int cell = n / NA;
                    int gj = cell % GW;
                    int gi = cell / GW;
                    int si = a / 3, ri = a % 3;
                    float s  = 0.5f * (float)(1 << si);
                    float r  = 0.5f * (float)(1 << ri);
                    float sr = sqrtf(r);
                    float ah = (s * sr) * 0.03125f;
                    float aw = (s / sr) * 0.03125f;
                    float ci = ((float)gi + 0.5f) * (1.0f / 128.0f);
                    float cj = ((float)gj + 0.5f) * (1.0f / 128.0f);
                    const float* t = ibase + (size_t)n * NC;
                    float di = ci + t[0] * ah;
                    float dj = cj + t[1] * aw;
                    float dh = ah * expf(t[2]);
                    float dw = aw * expf(t[3]);
                    c_box[i]   = make_float4(di, dj, dh, dw);
                    cor[i]     = make_float4(di - dh * 0.5f, dj - dw * 0.5f,
                                             di + dh * 0.5f, dj + dw * 0.5f);
                    c_score[i] = score;
                    c_idx[i]   = n;
                }
            }
        }
        if (tid == 0) s_any = 0;
        __syncthreads();

        // IoU suppression bit-matrix over first NMSW candidates
        const int Wlim = min(M, NMSW);
        {
            int rrr = tid >> 2, wi = tid & 3;
            u32 mask = 0;
            if (rrr < Wlim) {
                float4 a = cor[rrr];
                float aar = (a.z - a.x) * (a.w - a.y);
                int cbase = wi * 32;
                #pragma unroll 4
                for (int b = 0; b < 32; b++) {
                    int c = cbase + b;
                    if (c > rrr && c < Wlim) {
                        float4 bb = cor[c];
                        float ti = fmaxf(a.x, bb.x), tj = fmaxf(a.y, bb.y);
                        float bi = fminf(a.z, bb.z), bj = fminf(a.w, bb.w);
                        float inter = fmaxf(bi - ti, 0.0f) * fmaxf(bj - tj, 0.0f);
                        float bar = (bb.z - bb.x) * (bb.w - bb.y);
                        float uni = aar + bar - inter;
                        if (inter / fmaxf(uni, 1e-12f) > IOU_TH) mask |= (1u << b);
                    }
                }
            }
            rowsw[rrr][wi] = mask;
            if (tid < 4) rowsw[NMSW][tid] = 0;       // prefetch pad
            if (mask) atomicOr(&s_any, 1u);          // rare
        }
        __syncthreads();

        if (s_any == 0) {
            // zero suppression matrix => greedy keeps the prefix (exact)
            int nk = min(Wlim, MAXDET);
            if (tid < nk) kept_rank[tid] = tid;
            if (tid == 0) s_nk = nk;
        } else if (tid == 0) {
            const uint4* rv = (const uint4*)rowsw;
            u32 s0 = 0, s1 = 0, s2 = 0, s3 = 0;
            int nk = 0;
            uint4 rr = rv[0];
            for (int c = 0; c < Wlim && nk < MAXDET; ++c) {
                uint4 cur = rr;
                rr = rv[c + 1];
                u32 sw = (c < 64) ? ((c < 32) ? s0 : s1) : ((c < 96) ? s2 : s3);
                if (!((sw >> (c & 31)) & 1u)) {
                    kept_rank[nk++] = c;
                    s0 |= cur.x; s1 |= cur.y; s2 |= cur.z; s3 |= cur.w;
                }
            }
            s_nk = nk;
        }
        __syncthreads();

        // rare: continue serial greedy NMS past the window
        if (s_nk < MAXDET && M > Wlim) {
            if (tid < 32) {
                int nk = s_nk;
                float kc0[4], kc1[4], kc2[4], kc3[4], kar[4];
                #pragma unroll
                for (int sdx = 0; sdx < 4; ++sdx) {
                    int k = sdx * 32 + lane;
                    if (k < nk) {
                        float4 a = cor[kept_rank[k]];
                        kc0[sdx] = a.x; kc1[sdx] = a.y; kc2[sdx] = a.z; kc3[sdx] = a.w;
                        kar[sdx] = (a.z - a.x) * (a.w - a.y);
                    }
                }
                #pragma unroll 1
                for (int c = Wlim; c < M && nk < MAXDET; ++c) {
                    float4 a = cor[c];
                    float ar = (a.z - a.x) * (a.w - a.y);
                    bool pred = false;
                    #pragma unroll
                    for (int sdx = 0; sdx < 4; ++sdx) {
                        int k = sdx * 32 + lane;
                        if (k < nk) {
                            float ti = fmaxf(a.x, kc0[sdx]);
                            float tj = fmaxf(a.y, kc1[sdx]);
                            float bi = fminf(a.z, kc2[sdx]);
                            float bj = fminf(a.w, kc3[sdx]);
                            float inter = fmaxf(bi - ti, 0.0f) * fmaxf(bj - tj, 0.0f);
                            float uni = kar[sdx] + ar - inter;
                            pred |= (inter / fmaxf(uni, 1e-12f)) > IOU_TH;
                        }
                    }
                    if (!__ballot_sync(0xffffffffu, pred)) {
                        int slot = nk >> 5, ln = nk & 31;
                        if (lane == ln) {
                            #pragma unroll
                            for (int sdx = 0; sdx < 4; ++sdx) {
                                if (slot == sdx) {
                                    kc0[sdx] = a.x; kc1[sdx] = a.y;
                                    kc2[sdx] = a.z; kc3[sdx] = a.w; kar[sdx] = ar;
                                }
                            }
                            kept_rank[nk] = c;
                        }
                        nk++;
                    }
                }
                if (lane == 0) s_nk = nk;
            }
            __syncthreads();
        }

        // exactness post-check: fast set exhausted with <100 kept -> redo on full set
        if (tid == 0) s_flag = (!full && attempt == 0 && s_nk < MAXDET) ? 1 : 0;
        __syncthreads();
        if (!s_flag) break;

        full = true;
        if (tid == 0) s_fcnt = 0;
        __syncthreads();
        for (int i = tid; i < CAP; i += NT) keys[i] = 0ull;
        __syncthreads();
        for (int n = tid; n < NANCH; n += NT) {
            float s = ibase[(size_t)n * NC + 5];
            if (s >= SCORE_TH) {
                int pos = atomicAdd(&s_fcnt, 1);
                if (pos < CAP) keys[pos] = pack_key(s, n);
            }
        }
        __syncthreads();
        M = min(min(s_fcnt, CAP), TOPK);
        for (int k = 2; k <= CAP; k <<= 1)
            for (int j = k >> 1; j; j >>= 1) {
                for (int t = tid; t < CAP / 2; t += NT) {
                    int i = ((t & ~(j - 1)) << 1) | (t & (j - 1));
                    int p = i | j;
                    u64 a = keys[i], bb = keys[p];
                    bool desc = ((i & k) == 0);
                    if (desc ? (a < bb) : (a > bb)) { keys[i] = bb; keys[p] = a; }
                }
                __syncthreads();
            }
    }

    // ---- epilogue ----
    const int nk = s_nk;
    if (!full) {
        if (tid < MAXDET) {
            float* o = out + (size_t)img * MAXDET * 6 + tid * 6;
            if (tid < nk) {
                int c = kept_rank[tid];
                float4 bx = c_box[c];
                o[0] = bx.x; o[1] = bx.y; o[2] = bx.z; o[3] = bx.w;
                o[4] = c_lab[c];
                o[5] = c_score[c];
            } else {
                o[0] = 0.0f; o[1] = 0.0f; o[2] = 0.0f;
                o[3] = 0.0f; o[4] = 0.0f; o[5] = 0.0f;
            }
        }
    } else {
        #pragma unroll 1
        for (int row = tid >> 3; row < MAXDET; row += NT / 8) {
            const int sub = tid & 7;
            float* o = out + (size_t)img * MAXDET * 6 + row * 6;
            const bool live = row < nk;
            int c = live ? kept_rank[row] : 0;
            int n = live ? c_idx[c] : 0;
            float bv = -1e38f; int bidx = 1 << 30;
            if (live) {
                const float* cls = ibase + (size_t)n * NC + 6;
                #pragma unroll
                for (int t = 0; t < 10; t++) {
                    int cc = sub + t * 8;
                    float v = __ldg(cls + cc);
                    if (v > bv) { bv = v; bidx = cc; }
                }
            }
            #pragma unroll
            for (int off = 4; off; off >>= 1) {
                float ov = __shfl_down_sync(0xffffffffu, bv, off, 8);
                int   oi = __shfl_down_sync(0xffffffffu, bidx, off, 8);
                if (ov > bv || (ov == bv && oi < bidx)) { bv = ov; bidx = oi; }
            }
            if (live) {
                if (sub == 0) {
                    float4 bx = c_box[c];
                    o[0] = bx.x; o[1] = bx.y; o[2] = bx.z; o[3] = bx.w;
                    o[4] = (float)bidx;
                    o[5] = c_score[c];
                }
            } else {
                if (sub < 6) o[sub] = 0.0f;
            }
        }
    }
}

extern "C" void kernel_launch(void* const* d_in, const int* in_sizes, int n_in,
                              void* d_out, int out_size) {
    (void)in_sizes; (void)n_in; (void)out_size;
    const float* in = (const float*)d_in[0];
    float* out = (float*)d_out;

    prefilter_kernel<<<dim3(K1B, NIMG), K1T>>>(in);
    topk_nms_kernel<<<NIMG, NT>>>(in, out);
}